// round 10
// baseline (speedup 1.0000x reference)
#include <cuda_runtime.h>
#include <cuda_bf16.h>
#include <cuda_fp16.h>
#include <math.h>
#include <stdint.h>

#define NB       8192      // batch B
#define E_DIM    1024
#define P_DIM    512
#define D_DIM    1024      // 2P
#define M2       16384     // 2B rows in projection GEMM

// Scratch (no allocations allowed)
__device__ __nv_bfloat16 g_zb[(size_t)NB * D_DIM];      // 16 MB bf16 proj output z
__device__ __half g_znh[(size_t)NB * D_DIM];            // 16 MB f16 normalized
__device__ __nv_bfloat16 g_xh[(size_t)NB * 2 * E_DIM];  // 32 MB bf16 relu(x)
__device__ __nv_bfloat16 g_wh[(size_t)E_DIM * P_DIM];   // 1 MB bf16 w
__device__ float g_rowsum[NB];
__device__ float g_pos[NB];

// ---------------------------------------------------------------------------
// PTX helpers (sm_80-era only)
// ---------------------------------------------------------------------------
__device__ __forceinline__ uint32_t smem_u32(const void* p) {
    uint32_t a;
    asm("{ .reg .u64 t; cvta.to.shared.u64 t, %1; cvt.u32.u64 %0, t; }" : "=r"(a) : "l"(p));
    return a;
}
__device__ __forceinline__ void cp_async16(uint32_t dst, const void* src) {
    asm volatile("cp.async.cg.shared.global [%0], [%1], 16;" :: "r"(dst), "l"(src));
}
#define CP_COMMIT() asm volatile("cp.async.commit_group;" ::: "memory")
#define CP_WAIT(N)  asm volatile("cp.async.wait_group %0;" :: "n"(N) : "memory")

__device__ __forceinline__ void ldsm_x4(uint32_t& r0, uint32_t& r1, uint32_t& r2,
                                        uint32_t& r3, uint32_t addr) {
    asm volatile("ldmatrix.sync.aligned.m8n8.x4.shared.b16 {%0,%1,%2,%3}, [%4];"
                 : "=r"(r0), "=r"(r1), "=r"(r2), "=r"(r3) : "r"(addr));
}
__device__ __forceinline__ void ldsm_x4_t(uint32_t& r0, uint32_t& r1, uint32_t& r2,
                                          uint32_t& r3, uint32_t addr) {
    asm volatile("ldmatrix.sync.aligned.m8n8.x4.trans.shared.b16 {%0,%1,%2,%3}, [%4];"
                 : "=r"(r0), "=r"(r1), "=r"(r2), "=r"(r3) : "r"(addr));
}
__device__ __forceinline__ void mma_bf16(float* c, const uint32_t* a, const uint32_t* b) {
    asm volatile(
        "mma.sync.aligned.m16n8k16.row.col.f32.bf16.bf16.f32 "
        "{%0,%1,%2,%3}, {%4,%5,%6,%7}, {%8,%9}, {%0,%1,%2,%3};"
        : "+f"(c[0]), "+f"(c[1]), "+f"(c[2]), "+f"(c[3])
        : "r"(a[0]), "r"(a[1]), "r"(a[2]), "r"(a[3]), "r"(b[0]), "r"(b[1]));
}
// f16 inputs, f16 accumulators (2 regs)
__device__ __forceinline__ void mma_f16(uint32_t* c, const uint32_t* a, const uint32_t* b) {
    asm volatile(
        "mma.sync.aligned.m16n8k16.row.col.f16.f16.f16.f16 "
        "{%0,%1}, {%2,%3,%4,%5}, {%6,%7}, {%0,%1};"
        : "+r"(c[0]), "+r"(c[1])
        : "r"(a[0]), "r"(a[1]), "r"(a[2]), "r"(a[3]), "r"(b[0]), "r"(b[1]));
}

// ---------------------------------------------------------------------------
// Kernel 0: convert relu(x)->bf16 (g_xh) and w->bf16 (g_wh)
// ---------------------------------------------------------------------------
#define XCVT_BLOCKS 16384
#define WCVT_BLOCKS 512
__global__ __launch_bounds__(256) void convert_kernel(const float* __restrict__ x,
                                                      const float* __restrict__ w) {
    const int tid = threadIdx.x;
    if (blockIdx.x < XCVT_BLOCKS) {
        const size_t i = ((size_t)blockIdx.x * 256 + tid);
        float4 v = *(const float4*)(x + i * 4);
        __nv_bfloat162 p0 = __floats2bfloat162_rn(fmaxf(v.x, 0.f), fmaxf(v.y, 0.f));
        __nv_bfloat162 p1 = __floats2bfloat162_rn(fmaxf(v.z, 0.f), fmaxf(v.w, 0.f));
        uint2 o; o.x = *(uint32_t*)&p0; o.y = *(uint32_t*)&p1;
        *(uint2*)(g_xh + i * 4) = o;
    } else {
        const size_t i = ((size_t)(blockIdx.x - XCVT_BLOCKS) * 256 + tid);
        float4 v = *(const float4*)(w + i * 4);
        __nv_bfloat162 p0 = __floats2bfloat162_rn(v.x, v.y);
        __nv_bfloat162 p1 = __floats2bfloat162_rn(v.z, v.w);
        uint2 o; o.x = *(uint32_t*)&p0; o.y = *(uint32_t*)&p1;
        *(uint2*)(g_wh + i * 4) = o;
    }
}

// ---------------------------------------------------------------------------
// Kernel 1: HMMA projection (R7 structure, unchanged), bf16 in/out, f32 acc.
// ---------------------------------------------------------------------------
#define AROW_BYTES  80
#define PA_BYTES    (128 * AROW_BYTES)
#define BROW_BYTES  272
#define PB_BYTES    (32 * BROW_BYTES)
#define PSTAGE      (PA_BYTES + PB_BYTES)
#define PSTAGES     4
#define PROJ_SMEM   (PSTAGES * PSTAGE)
#define PCHUNKS     (E_DIM / 32)

extern __shared__ char dsmem[];

__device__ __forceinline__ void proj_prefetch(uint32_t stA, uint32_t stB,
                                              int m0, int n0, int kb, int tid) {
#pragma unroll
    for (int it = 0; it < 4; it++) {
        const int j = tid + it * 128;
        const int row = j >> 2, seg = j & 3;
        const int r = m0 + row;
        const __nv_bfloat16* src = g_xh + (size_t)(r & (NB - 1)) * 2048
                                 + (size_t)(r >> 13) * 1024 + kb + (seg << 3);
        cp_async16(stA + row * AROW_BYTES + seg * 16, src);
    }
#pragma unroll
    for (int it = 0; it < 4; it++) {
        const int j = tid + it * 128;
        const int row = j >> 4, seg = j & 15;
        const __nv_bfloat16* src = g_wh + (size_t)(kb + row) * P_DIM + n0 + (seg << 3);
        cp_async16(stB + row * BROW_BYTES + seg * 16, src);
    }
}

__global__ __launch_bounds__(128)
void proj_kernel(const float* __restrict__ bias) {
    const int tid = threadIdx.x;
    const int wid = tid >> 5;
    const int lane = tid & 31;
    const int warp_m = wid >> 1;
    const int warp_n = wid & 1;
    const int m0 = blockIdx.y * 128;
    const int n0 = blockIdx.x * 128;

    const uint32_t sbase = smem_u32(dsmem);
    uint32_t stA[PSTAGES], stB[PSTAGES];
#pragma unroll
    for (int s = 0; s < PSTAGES; s++) {
        stA[s] = sbase + s * PSTAGE;
        stB[s] = stA[s] + PA_BYTES;
    }

    const uint32_t aOff = (warp_m * 64 + (lane & 15)) * AROW_BYTES + (lane >> 4) * 16;
    const uint32_t bRow = (lane & 7) + ((lane >> 3) & 1) * 8;
    const uint32_t bCol = warp_n * 64 + (lane >> 4) * 8;

    float acc[4][8][4];
#pragma unroll
    for (int mi = 0; mi < 4; mi++)
#pragma unroll
        for (int ni = 0; ni < 8; ni++)
#pragma unroll
            for (int k = 0; k < 4; k++) acc[mi][ni][k] = 0.f;

    proj_prefetch(stA[0], stB[0], m0, n0, 0, tid);  CP_COMMIT();
    proj_prefetch(stA[1], stB[1], m0, n0, 32, tid); CP_COMMIT();
    proj_prefetch(stA[2], stB[2], m0, n0, 64, tid); CP_COMMIT();

    for (int kc = 0; kc < PCHUNKS; kc++) {
        CP_WAIT(2);
        __syncthreads();
        const int s = kc % PSTAGES;

        uint32_t aF[2][4][4], bF[2][4][4];
#pragma unroll
        for (int ks = 0; ks < 2; ks++) {
#pragma unroll
            for (int mi = 0; mi < 4; mi++)
                ldsm_x4(aF[ks][mi][0], aF[ks][mi][1], aF[ks][mi][2], aF[ks][mi][3],
                        stA[s] + aOff + mi * 16 * AROW_BYTES + ks * 32);
#pragma unroll
            for (int p = 0; p < 4; p++)
                ldsm_x4_t(bF[ks][p][0], bF[ks][p][1], bF[ks][p][2], bF[ks][p][3],
                          stB[s] + (ks * 16 + bRow) * BROW_BYTES + (bCol + p * 16) * 2);
        }

        if (kc + 3 < PCHUNKS) {
            const int sn = (kc + 3) % PSTAGES;
            proj_prefetch(stA[sn], stB[sn], m0, n0, (kc + 3) * 32, tid);
        }
        CP_COMMIT();

#pragma unroll
        for (int ks = 0; ks < 2; ks++)
#pragma unroll
            for (int mi = 0; mi < 4; mi++)
#pragma unroll
                for (int ni = 0; ni < 8; ni++)
                    mma_bf16(acc[mi][ni], aF[ks][mi], &bF[ks][ni >> 1][(ni & 1) * 2]);
    }

    const int cb = n0 + warp_n * 64 + (lane & 3) * 2;
#pragma unroll
    for (int mi = 0; mi < 4; mi++)
#pragma unroll
        for (int half8 = 0; half8 < 2; half8++) {
            const int r = m0 + warp_m * 64 + mi * 16 + half8 * 8 + (lane >> 2);
            const int ib = r & (NB - 1);
            const int hh = r >> 13;
            __nv_bfloat16* outRow = g_zb + (size_t)ib * D_DIM + hh * P_DIM;
#pragma unroll
            for (int ni = 0; ni < 8; ni++) {
                const int c = cb + ni * 8;
                __nv_bfloat162 v = __floats2bfloat162_rn(
                    acc[mi][ni][half8 * 2 + 0] + __ldg(bias + c),
                    acc[mi][ni][half8 * 2 + 1] + __ldg(bias + c + 1));
                *(uint32_t*)(outRow + c) = *(uint32_t*)&v;
            }
        }
}

// ---------------------------------------------------------------------------
// Kernel 2: per-row L2 normalize (bf16 in) -> f16 g_znh, zeroes g_rowsum
// ---------------------------------------------------------------------------
__global__ __launch_bounds__(256) void norm_kernel() {
    __shared__ float red[256];
    const __nv_bfloat16* row = g_zb + (size_t)blockIdx.x * D_DIM;
    uint2 u = *(const uint2*)(row + threadIdx.x * 4);
    __nv_bfloat162 b0 = *(__nv_bfloat162*)&u.x;
    __nv_bfloat162 b1 = *(__nv_bfloat162*)&u.y;
    float v0 = __bfloat162float(b0.x), v1 = __bfloat162float(b0.y);
    float v2 = __bfloat162float(b1.x), v3 = __bfloat162float(b1.y);
    red[threadIdx.x] = v0 * v0 + v1 * v1 + v2 * v2 + v3 * v3;
    __syncthreads();
    for (int off = 128; off > 0; off >>= 1) {
        if (threadIdx.x < off) red[threadIdx.x] += red[threadIdx.x + off];
        __syncthreads();
    }
    const float inv = 1.0f / fmaxf(sqrtf(red[0]), 1e-8f);
    __half2 p0 = __floats2half2_rn(v0 * inv, v1 * inv);
    __half2 p1 = __floats2half2_rn(v2 * inv, v3 * inv);
    uint2 o; o.x = *(uint32_t*)&p0; o.y = *(uint32_t*)&p1;
    *(uint2*)(g_znh + (size_t)blockIdx.x * D_DIM + threadIdx.x * 4) = o;
    if (threadIdx.x == 0) g_rowsum[blockIdx.x] = 0.f;
}

// ---------------------------------------------------------------------------
// Kernel 3: f16-acc HMMA sim GEMM (upper triangle), block 128x128,
// 8 warps (warp tile 64x32), BK=32, 4 stages, WAIT(2), fused softmax.
// ---------------------------------------------------------------------------
#define ROW_BYTES   80
#define TILE_BYTES  (128 * ROW_BYTES)
#define STAGE_BYTES (2 * TILE_BYTES)         // 20480
#define SSTAGES     4
#define SIM_SMEM    (SSTAGES * STAGE_BYTES)  // 81920
#define SCHUNKS     (D_DIM / 32)             // 32
#define TRI_BLOCKS  2080

__device__ __forceinline__ void sim_prefetch(uint32_t stageA, uint32_t stageB,
                                             int r0, int c0, int kb, int tid) {
#pragma unroll
    for (int it = 0; it < 2; it++) {
        const int i = tid + it * 256;
        const int row = i >> 2, seg = i & 3;
        const uint32_t d = row * ROW_BYTES + seg * 16;
        cp_async16(stageA + d, g_znh + (((size_t)(r0 + row)) << 10) + kb + (seg << 3));
        cp_async16(stageB + d, g_znh + (((size_t)(c0 + row)) << 10) + kb + (seg << 3));
    }
}

__global__ __launch_bounds__(256, 2)
void sim_kernel() {
    // map t -> (by, bx) upper triangle, bx >= by
    const int t = blockIdx.x;
    int by = (int)((129.0f - sqrtf(129.0f * 129.0f - 8.0f * (float)t)) * 0.5f);
    if (by > 63) by = 63;
    if (by < 0) by = 0;
    while (by * 64 - (by * (by - 1)) / 2 > t) by--;
    while ((by + 1) * 64 - ((by + 1) * by) / 2 <= t) by++;
    const int bx = by + (t - (by * 64 - (by * (by - 1)) / 2));

    const int tid = threadIdx.x;
    const int wid = tid >> 5;
    const int lane = tid & 31;
    const int warp_m = wid >> 2;             // 0..1 -> 64-row strips
    const int warp_n = wid & 3;              // 0..3 -> 32-col strips
    const int r0 = by * 128;
    const int c0 = bx * 128;

    const uint32_t sbase = smem_u32(dsmem);
    uint32_t stA[SSTAGES], stB[SSTAGES];
#pragma unroll
    for (int s = 0; s < SSTAGES; s++) {
        stA[s] = sbase + s * STAGE_BYTES;
        stB[s] = stA[s] + TILE_BYTES;
    }

    const uint32_t aOff = (warp_m * 64 + (lane & 15)) * ROW_BYTES + (lane >> 4) * 16;
    const uint32_t bOff = (warp_n * 32 + ((lane >> 4) & 1) * 8 + (lane & 7)) * ROW_BYTES
                        + ((lane >> 3) & 1) * 16;

    uint32_t acc[4][4][2];                   // f16x2 accumulators
#pragma unroll
    for (int mi = 0; mi < 4; mi++)
#pragma unroll
        for (int ni = 0; ni < 4; ni++) { acc[mi][ni][0] = 0u; acc[mi][ni][1] = 0u; }

    sim_prefetch(stA[0], stB[0], r0, c0, 0, tid);  CP_COMMIT();
    sim_prefetch(stA[1], stB[1], r0, c0, 32, tid); CP_COMMIT();
    sim_prefetch(stA[2], stB[2], r0, c0, 64, tid); CP_COMMIT();

    for (int kc = 0; kc < SCHUNKS; kc++) {
        CP_WAIT(2);
        __syncthreads();
        const int s = kc % SSTAGES;

        uint32_t aF[2][4][4], bF[2][2][4];
#pragma unroll
        for (int ks = 0; ks < 2; ks++) {
#pragma unroll
            for (int mi = 0; mi < 4; mi++)
                ldsm_x4(aF[ks][mi][0], aF[ks][mi][1], aF[ks][mi][2], aF[ks][mi][3],
                        stA[s] + aOff + mi * 16 * ROW_BYTES + ks * 32);
#pragma unroll
            for (int p = 0; p < 2; p++)
                ldsm_x4(bF[ks][p][0], bF[ks][p][1], bF[ks][p][2], bF[ks][p][3],
                        stB[s] + bOff + p * 16 * ROW_BYTES + ks * 32);
        }

        if (kc + 3 < SCHUNKS) {
            const int sn = (kc + 3) % SSTAGES;
            sim_prefetch(stA[sn], stB[sn], r0, c0, (kc + 3) * 32, tid);
        }
        CP_COMMIT();

#pragma unroll
        for (int ks = 0; ks < 2; ks++)
#pragma unroll
            for (int mi = 0; mi < 4; mi++)
#pragma unroll
                for (int ni = 0; ni < 4; ni++)
                    mma_f16(acc[mi][ni], aF[ks][mi], &bF[ks][ni >> 1][(ni & 1) * 2]);
    }

    // ---------------- fused epilogue ----------------
    const bool isDiag = (bx == by);
    const bool hasPos = (bx == (by ^ 32));
    const int groupID = lane >> 2, tIdx = lane & 3;
    const int rbase = r0 + warp_m * 64 + groupID;
    const int cbase = c0 + warp_n * 32 + tIdx * 2;

    float rs[4][2];                          // [mi][rowhalf]
    float cs[4][2];                          // [ni][colpair]
#pragma unroll
    for (int i = 0; i < 4; i++) { rs[i][0] = rs[i][1] = 0.f; cs[i][0] = cs[i][1] = 0.f; }

#pragma unroll
    for (int mi = 0; mi < 4; mi++)
#pragma unroll
        for (int ni = 0; ni < 4; ni++)
#pragma unroll
            for (int hh = 0; hh < 2; hh++) {
                const int r = rbase + mi * 16 + hh * 8;
                __half2 hv = *(__half2*)&acc[mi][ni][hh];
                float v[2] = {__half2float(hv.x), __half2float(hv.y)};
#pragma unroll
                for (int cc = 0; cc < 2; cc++) {
                    const int c = cbase + ni * 8 + cc;
                    const float logit = v[cc] * 10.0f;
                    if (hasPos && c == (r ^ 4096)) { g_pos[r] = logit; g_pos[c] = logit; }
                    float ev = __expf(logit - 10.0f);
                    if (isDiag && r == c) ev = 0.f;
                    rs[mi][hh] += ev;
                    cs[ni][cc] += ev;
                }
            }

    // rows: reduce over tIdx (lanes 1,2)
#pragma unroll
    for (int off = 1; off <= 2; off <<= 1)
#pragma unroll
        for (int mi = 0; mi < 4; mi++)
#pragma unroll
            for (int h = 0; h < 2; h++)
                rs[mi][h] += __shfl_xor_sync(0xffffffffu, rs[mi][h], off);
    {
        const int mi = tIdx;
        const int r = r0 + warp_m * 64 + mi * 16 + groupID;
        atomicAdd(&g_rowsum[r],     rs[mi][0]);
        atomicAdd(&g_rowsum[r + 8], rs[mi][1]);
    }

    // cols: reduce over groupID (lanes 4,8,16), off-diag only
    if (!isDiag) {
#pragma unroll
        for (int off = 4; off <= 16; off <<= 1)
#pragma unroll
            for (int ni = 0; ni < 4; ni++)
#pragma unroll
                for (int h = 0; h < 2; h++)
                    cs[ni][h] += __shfl_xor_sync(0xffffffffu, cs[ni][h], off);
        if (lane < 16) {
            const int ni = lane >> 2;
            const int c = c0 + warp_n * 32 + ni * 8 + (lane & 3) * 2;
            atomicAdd(&g_rowsum[c],     cs[ni][0]);
            atomicAdd(&g_rowsum[c + 1], cs[ni][1]);
        }
    }
}

// ---------------------------------------------------------------------------
// Kernel 4: nll_i = -pos_i + 10 + log(rowsum_i); out = mean(nll)
// ---------------------------------------------------------------------------
__global__ __launch_bounds__(1024) void final_kernel(float* __restrict__ out) {
    __shared__ float red[1024];
    float s = 0.f;
    for (int i = threadIdx.x; i < NB; i += 1024)
        s += -g_pos[i] + 10.0f + logf(g_rowsum[i]);
    red[threadIdx.x] = s;
    __syncthreads();
    for (int off = 512; off > 0; off >>= 1) {
        if (threadIdx.x < off) red[threadIdx.x] += red[threadIdx.x + off];
        __syncthreads();
    }
    if (threadIdx.x == 0) out[0] = red[0] / (float)NB;
}

// ---------------------------------------------------------------------------
extern "C" void kernel_launch(void* const* d_in, const int* in_sizes, int n_in,
                              void* d_out, int out_size) {
    const float* x = (const float*)d_in[0];
    const float* w = (const float*)d_in[1];
    const float* b = (const float*)d_in[2];
    float* out = (float*)d_out;

    cudaFuncSetAttribute(proj_kernel, cudaFuncAttributeMaxDynamicSharedMemorySize, PROJ_SMEM);
    cudaFuncSetAttribute(sim_kernel,  cudaFuncAttributeMaxDynamicSharedMemorySize, SIM_SMEM);

    convert_kernel<<<XCVT_BLOCKS + WCVT_BLOCKS, 256>>>(x, w);
    dim3 g1(P_DIM / 128, M2 / 128);
    proj_kernel<<<g1, 128, PROJ_SMEM>>>(b);
    norm_kernel<<<NB, 256>>>();
    sim_kernel<<<TRI_BLOCKS, 256, SIM_SMEM>>>();
    final_kernel<<<1, 1024>>>(out);
}

// round 11
// speedup vs baseline: 1.1175x; 1.1175x over previous
#include <cuda_runtime.h>
#include <cuda_bf16.h>
#include <cuda_fp16.h>
#include <math.h>
#include <stdint.h>

#define NB       8192      // batch B
#define E_DIM    1024
#define P_DIM    512
#define D_DIM    1024      // 2P
#define M2       16384     // 2B rows in projection GEMM

// Scratch (no allocations allowed)
__device__ __nv_bfloat16 g_zb[(size_t)NB * D_DIM];      // 16 MB bf16 proj output z
__device__ __half g_znh[(size_t)NB * D_DIM];            // 16 MB f16 normalized
__device__ __nv_bfloat16 g_xh[(size_t)NB * 2 * E_DIM];  // 32 MB bf16 relu(x)
__device__ __nv_bfloat16 g_wh[(size_t)E_DIM * P_DIM];   // 1 MB bf16 w
__device__ float g_rowsum[NB];
__device__ float g_pos[NB];

// ---------------------------------------------------------------------------
// PTX helpers (sm_80-era only)
// ---------------------------------------------------------------------------
__device__ __forceinline__ uint32_t smem_u32(const void* p) {
    uint32_t a;
    asm("{ .reg .u64 t; cvta.to.shared.u64 t, %1; cvt.u32.u64 %0, t; }" : "=r"(a) : "l"(p));
    return a;
}
__device__ __forceinline__ void cp_async16(uint32_t dst, const void* src) {
    asm volatile("cp.async.cg.shared.global [%0], [%1], 16;" :: "r"(dst), "l"(src));
}
#define CP_COMMIT() asm volatile("cp.async.commit_group;" ::: "memory")
#define CP_WAIT(N)  asm volatile("cp.async.wait_group %0;" :: "n"(N) : "memory")

__device__ __forceinline__ void ldsm_x4(uint32_t& r0, uint32_t& r1, uint32_t& r2,
                                        uint32_t& r3, uint32_t addr) {
    asm volatile("ldmatrix.sync.aligned.m8n8.x4.shared.b16 {%0,%1,%2,%3}, [%4];"
                 : "=r"(r0), "=r"(r1), "=r"(r2), "=r"(r3) : "r"(addr));
}
__device__ __forceinline__ void ldsm_x4_t(uint32_t& r0, uint32_t& r1, uint32_t& r2,
                                          uint32_t& r3, uint32_t addr) {
    asm volatile("ldmatrix.sync.aligned.m8n8.x4.trans.shared.b16 {%0,%1,%2,%3}, [%4];"
                 : "=r"(r0), "=r"(r1), "=r"(r2), "=r"(r3) : "r"(addr));
}
__device__ __forceinline__ void mma_bf16(float* c, const uint32_t* a, const uint32_t* b) {
    asm volatile(
        "mma.sync.aligned.m16n8k16.row.col.f32.bf16.bf16.f32 "
        "{%0,%1,%2,%3}, {%4,%5,%6,%7}, {%8,%9}, {%0,%1,%2,%3};"
        : "+f"(c[0]), "+f"(c[1]), "+f"(c[2]), "+f"(c[3])
        : "r"(a[0]), "r"(a[1]), "r"(a[2]), "r"(a[3]), "r"(b[0]), "r"(b[1]));
}
// f16 inputs, f16 accumulators (2 regs)
__device__ __forceinline__ void mma_f16(uint32_t* c, const uint32_t* a, const uint32_t* b) {
    asm volatile(
        "mma.sync.aligned.m16n8k16.row.col.f16.f16.f16.f16 "
        "{%0,%1}, {%2,%3,%4,%5}, {%6,%7}, {%0,%1};"
        : "+r"(c[0]), "+r"(c[1])
        : "r"(a[0]), "r"(a[1]), "r"(a[2]), "r"(a[3]), "r"(b[0]), "r"(b[1]));
}

// ---------------------------------------------------------------------------
// Kernel 0: convert relu(x)->bf16 (g_xh) and w->bf16 (g_wh)
// ---------------------------------------------------------------------------
#define XCVT_BLOCKS 16384
#define WCVT_BLOCKS 512
__global__ __launch_bounds__(256) void convert_kernel(const float* __restrict__ x,
                                                      const float* __restrict__ w) {
    const int tid = threadIdx.x;
    if (blockIdx.x < XCVT_BLOCKS) {
        const size_t i = ((size_t)blockIdx.x * 256 + tid);
        float4 v = *(const float4*)(x + i * 4);
        __nv_bfloat162 p0 = __floats2bfloat162_rn(fmaxf(v.x, 0.f), fmaxf(v.y, 0.f));
        __nv_bfloat162 p1 = __floats2bfloat162_rn(fmaxf(v.z, 0.f), fmaxf(v.w, 0.f));
        uint2 o; o.x = *(uint32_t*)&p0; o.y = *(uint32_t*)&p1;
        *(uint2*)(g_xh + i * 4) = o;
    } else {
        const size_t i = ((size_t)(blockIdx.x - XCVT_BLOCKS) * 256 + tid);
        float4 v = *(const float4*)(w + i * 4);
        __nv_bfloat162 p0 = __floats2bfloat162_rn(v.x, v.y);
        __nv_bfloat162 p1 = __floats2bfloat162_rn(v.z, v.w);
        uint2 o; o.x = *(uint32_t*)&p0; o.y = *(uint32_t*)&p1;
        *(uint2*)(g_wh + i * 4) = o;
    }
}

// ---------------------------------------------------------------------------
// Kernel 1: HMMA projection (R7 structure, unchanged), bf16 in/out, f32 acc.
// ---------------------------------------------------------------------------
#define AROW_BYTES  80
#define PA_BYTES    (128 * AROW_BYTES)
#define BROW_BYTES  272
#define PB_BYTES    (32 * BROW_BYTES)
#define PSTAGE      (PA_BYTES + PB_BYTES)
#define PSTAGES     4
#define PROJ_SMEM   (PSTAGES * PSTAGE)
#define PCHUNKS     (E_DIM / 32)

extern __shared__ char dsmem[];

__device__ __forceinline__ void proj_prefetch(uint32_t stA, uint32_t stB,
                                              int m0, int n0, int kb, int tid) {
#pragma unroll
    for (int it = 0; it < 4; it++) {
        const int j = tid + it * 128;
        const int row = j >> 2, seg = j & 3;
        const int r = m0 + row;
        const __nv_bfloat16* src = g_xh + (size_t)(r & (NB - 1)) * 2048
                                 + (size_t)(r >> 13) * 1024 + kb + (seg << 3);
        cp_async16(stA + row * AROW_BYTES + seg * 16, src);
    }
#pragma unroll
    for (int it = 0; it < 4; it++) {
        const int j = tid + it * 128;
        const int row = j >> 4, seg = j & 15;
        const __nv_bfloat16* src = g_wh + (size_t)(kb + row) * P_DIM + n0 + (seg << 3);
        cp_async16(stB + row * BROW_BYTES + seg * 16, src);
    }
}

__global__ __launch_bounds__(128)
void proj_kernel(const float* __restrict__ bias) {
    const int tid = threadIdx.x;
    const int wid = tid >> 5;
    const int lane = tid & 31;
    const int warp_m = wid >> 1;
    const int warp_n = wid & 1;
    const int m0 = blockIdx.y * 128;
    const int n0 = blockIdx.x * 128;

    const uint32_t sbase = smem_u32(dsmem);
    uint32_t stA[PSTAGES], stB[PSTAGES];
#pragma unroll
    for (int s = 0; s < PSTAGES; s++) {
        stA[s] = sbase + s * PSTAGE;
        stB[s] = stA[s] + PA_BYTES;
    }

    const uint32_t aOff = (warp_m * 64 + (lane & 15)) * AROW_BYTES + (lane >> 4) * 16;
    const uint32_t bRow = (lane & 7) + ((lane >> 3) & 1) * 8;
    const uint32_t bCol = warp_n * 64 + (lane >> 4) * 8;

    float acc[4][8][4];
#pragma unroll
    for (int mi = 0; mi < 4; mi++)
#pragma unroll
        for (int ni = 0; ni < 8; ni++)
#pragma unroll
            for (int k = 0; k < 4; k++) acc[mi][ni][k] = 0.f;

    proj_prefetch(stA[0], stB[0], m0, n0, 0, tid);  CP_COMMIT();
    proj_prefetch(stA[1], stB[1], m0, n0, 32, tid); CP_COMMIT();
    proj_prefetch(stA[2], stB[2], m0, n0, 64, tid); CP_COMMIT();

    for (int kc = 0; kc < PCHUNKS; kc++) {
        CP_WAIT(2);
        __syncthreads();
        const int s = kc % PSTAGES;

        uint32_t aF[2][4][4], bF[2][4][4];
#pragma unroll
        for (int ks = 0; ks < 2; ks++) {
#pragma unroll
            for (int mi = 0; mi < 4; mi++)
                ldsm_x4(aF[ks][mi][0], aF[ks][mi][1], aF[ks][mi][2], aF[ks][mi][3],
                        stA[s] + aOff + mi * 16 * AROW_BYTES + ks * 32);
#pragma unroll
            for (int p = 0; p < 4; p++)
                ldsm_x4_t(bF[ks][p][0], bF[ks][p][1], bF[ks][p][2], bF[ks][p][3],
                          stB[s] + (ks * 16 + bRow) * BROW_BYTES + (bCol + p * 16) * 2);
        }

        if (kc + 3 < PCHUNKS) {
            const int sn = (kc + 3) % PSTAGES;
            proj_prefetch(stA[sn], stB[sn], m0, n0, (kc + 3) * 32, tid);
        }
        CP_COMMIT();

#pragma unroll
        for (int ks = 0; ks < 2; ks++)
#pragma unroll
            for (int mi = 0; mi < 4; mi++)
#pragma unroll
                for (int ni = 0; ni < 8; ni++)
                    mma_bf16(acc[mi][ni], aF[ks][mi], &bF[ks][ni >> 1][(ni & 1) * 2]);
    }

    const int cb = n0 + warp_n * 64 + (lane & 3) * 2;
#pragma unroll
    for (int mi = 0; mi < 4; mi++)
#pragma unroll
        for (int half8 = 0; half8 < 2; half8++) {
            const int r = m0 + warp_m * 64 + mi * 16 + half8 * 8 + (lane >> 2);
            const int ib = r & (NB - 1);
            const int hh = r >> 13;
            __nv_bfloat16* outRow = g_zb + (size_t)ib * D_DIM + hh * P_DIM;
#pragma unroll
            for (int ni = 0; ni < 8; ni++) {
                const int c = cb + ni * 8;
                __nv_bfloat162 v = __floats2bfloat162_rn(
                    acc[mi][ni][half8 * 2 + 0] + __ldg(bias + c),
                    acc[mi][ni][half8 * 2 + 1] + __ldg(bias + c + 1));
                *(uint32_t*)(outRow + c) = *(uint32_t*)&v;
            }
        }
}

// ---------------------------------------------------------------------------
// Kernel 2: per-row L2 normalize (bf16 in) -> f16 g_znh, zeroes g_rowsum
// ---------------------------------------------------------------------------
__global__ __launch_bounds__(256) void norm_kernel() {
    __shared__ float red[256];
    const __nv_bfloat16* row = g_zb + (size_t)blockIdx.x * D_DIM;
    uint2 u = *(const uint2*)(row + threadIdx.x * 4);
    __nv_bfloat162 b0 = *(__nv_bfloat162*)&u.x;
    __nv_bfloat162 b1 = *(__nv_bfloat162*)&u.y;
    float v0 = __bfloat162float(b0.x), v1 = __bfloat162float(b0.y);
    float v2 = __bfloat162float(b1.x), v3 = __bfloat162float(b1.y);
    red[threadIdx.x] = v0 * v0 + v1 * v1 + v2 * v2 + v3 * v3;
    __syncthreads();
    for (int off = 128; off > 0; off >>= 1) {
        if (threadIdx.x < off) red[threadIdx.x] += red[threadIdx.x + off];
        __syncthreads();
    }
    const float inv = 1.0f / fmaxf(sqrtf(red[0]), 1e-8f);
    __half2 p0 = __floats2half2_rn(v0 * inv, v1 * inv);
    __half2 p1 = __floats2half2_rn(v2 * inv, v3 * inv);
    uint2 o; o.x = *(uint32_t*)&p0; o.y = *(uint32_t*)&p1;
    *(uint2*)(g_znh + (size_t)blockIdx.x * D_DIM + threadIdx.x * 4) = o;
    if (threadIdx.x == 0) g_rowsum[blockIdx.x] = 0.f;
}

// ---------------------------------------------------------------------------
// Kernel 3: f16-acc HMMA sim GEMM (upper triangle), block 128x128,
// 4 warps (warp tile 64x64), BK=32, 3 stages, WAIT(1), 3 CTAs/SM target.
// ---------------------------------------------------------------------------
#define ROW_BYTES   80
#define TILE_BYTES  (128 * ROW_BYTES)
#define STAGE_BYTES (2 * TILE_BYTES)         // 20480
#define SSTAGES     3
#define SIM_SMEM    (SSTAGES * STAGE_BYTES)  // 61440
#define SCHUNKS     (D_DIM / 32)             // 32
#define TRI_BLOCKS  2080

__device__ __forceinline__ void sim_prefetch(uint32_t stageA, uint32_t stageB,
                                             int r0, int c0, int kb, int tid) {
#pragma unroll
    for (int it = 0; it < 4; it++) {
        const int i = tid + it * 128;
        const int row = i >> 2, seg = i & 3;
        const uint32_t d = row * ROW_BYTES + seg * 16;
        cp_async16(stageA + d, g_znh + (((size_t)(r0 + row)) << 10) + kb + (seg << 3));
        cp_async16(stageB + d, g_znh + (((size_t)(c0 + row)) << 10) + kb + (seg << 3));
    }
}

__global__ __launch_bounds__(128, 3)
void sim_kernel() {
    // map t -> (by, bx) upper triangle, bx >= by
    const int t = blockIdx.x;
    int by = (int)((129.0f - sqrtf(129.0f * 129.0f - 8.0f * (float)t)) * 0.5f);
    if (by > 63) by = 63;
    if (by < 0) by = 0;
    while (by * 64 - (by * (by - 1)) / 2 > t) by--;
    while ((by + 1) * 64 - ((by + 1) * by) / 2 <= t) by++;
    const int bx = by + (t - (by * 64 - (by * (by - 1)) / 2));

    const int tid = threadIdx.x;
    const int wid = tid >> 5;
    const int lane = tid & 31;
    const int warp_m = wid >> 1;             // 0..1
    const int warp_n = wid & 1;              // 0..1
    const int r0 = by * 128;
    const int c0 = bx * 128;

    const uint32_t sbase = smem_u32(dsmem);
    uint32_t stA[SSTAGES], stB[SSTAGES];
#pragma unroll
    for (int s = 0; s < SSTAGES; s++) {
        stA[s] = sbase + s * STAGE_BYTES;
        stB[s] = stA[s] + TILE_BYTES;
    }

    const uint32_t aOff = (warp_m * 64 + (lane & 15)) * ROW_BYTES + (lane >> 4) * 16;
    const uint32_t bOff = (warp_n * 64 + ((lane >> 4) & 1) * 8 + (lane & 7)) * ROW_BYTES
                        + ((lane >> 3) & 1) * 16;

    uint32_t acc[4][8][2];                   // f16x2 accumulators
#pragma unroll
    for (int mi = 0; mi < 4; mi++)
#pragma unroll
        for (int ni = 0; ni < 8; ni++) { acc[mi][ni][0] = 0u; acc[mi][ni][1] = 0u; }

    sim_prefetch(stA[0], stB[0], r0, c0, 0, tid);  CP_COMMIT();
    sim_prefetch(stA[1], stB[1], r0, c0, 32, tid); CP_COMMIT();

    for (int kc = 0; kc < SCHUNKS; kc++) {
        CP_WAIT(1);
        __syncthreads();
        const int s = kc % SSTAGES;

        uint32_t aF[2][4][4], bF[2][4][4];
#pragma unroll
        for (int ks = 0; ks < 2; ks++) {
#pragma unroll
            for (int mi = 0; mi < 4; mi++)
                ldsm_x4(aF[ks][mi][0], aF[ks][mi][1], aF[ks][mi][2], aF[ks][mi][3],
                        stA[s] + aOff + mi * 16 * ROW_BYTES + ks * 32);
#pragma unroll
            for (int p = 0; p < 4; p++)
                ldsm_x4(bF[ks][p][0], bF[ks][p][1], bF[ks][p][2], bF[ks][p][3],
                        stB[s] + bOff + p * 16 * ROW_BYTES + ks * 32);
        }

        if (kc + 2 < SCHUNKS) {
            const int sn = (kc + 2) % SSTAGES;
            sim_prefetch(stA[sn], stB[sn], r0, c0, (kc + 2) * 32, tid);
        }
        CP_COMMIT();

#pragma unroll
        for (int ks = 0; ks < 2; ks++)
#pragma unroll
            for (int mi = 0; mi < 4; mi++)
#pragma unroll
                for (int ni = 0; ni < 8; ni++)
                    mma_f16(acc[mi][ni], aF[ks][mi], &bF[ks][ni >> 1][(ni & 1) * 2]);
    }

    // ---------------- fused epilogue ----------------
    const bool isDiag = (bx == by);
    const bool hasPos = (bx == (by ^ 32));
    const int groupID = lane >> 2, tIdx = lane & 3;
    const int rbase = r0 + warp_m * 64 + groupID;
    const int cbase = c0 + warp_n * 64 + tIdx * 2;

    float rs[4][2];                          // [mi][rowhalf]
    float cs[8][2];                          // [ni][colpair]
#pragma unroll
    for (int i = 0; i < 4; i++) { rs[i][0] = rs[i][1] = 0.f; }
#pragma unroll
    for (int i = 0; i < 8; i++) { cs[i][0] = cs[i][1] = 0.f; }

#pragma unroll
    for (int mi = 0; mi < 4; mi++)
#pragma unroll
        for (int ni = 0; ni < 8; ni++)
#pragma unroll
            for (int hh = 0; hh < 2; hh++) {
                const int r = rbase + mi * 16 + hh * 8;
                __half2 hv = *(__half2*)&acc[mi][ni][hh];
                float v[2] = {__half2float(hv.x), __half2float(hv.y)};
#pragma unroll
                for (int cc = 0; cc < 2; cc++) {
                    const int c = cbase + ni * 8 + cc;
                    const float logit = v[cc] * 10.0f;
                    if (hasPos && c == (r ^ 4096)) { g_pos[r] = logit; g_pos[c] = logit; }
                    float ev = __expf(logit - 10.0f);
                    if (isDiag && r == c) ev = 0.f;
                    rs[mi][hh] += ev;
                    cs[ni][cc] += ev;
                }
            }

    // rows: reduce over tIdx (xor 1,2)
#pragma unroll
    for (int off = 1; off <= 2; off <<= 1)
#pragma unroll
        for (int mi = 0; mi < 4; mi++)
#pragma unroll
            for (int h = 0; h < 2; h++)
                rs[mi][h] += __shfl_xor_sync(0xffffffffu, rs[mi][h], off);
    {
        const int mi = tIdx;
        const int r = r0 + warp_m * 64 + mi * 16 + groupID;
        atomicAdd(&g_rowsum[r],     rs[mi][0]);
        atomicAdd(&g_rowsum[r + 8], rs[mi][1]);
    }

    // cols: reduce over groupID (xor 4,8,16), off-diag only
    if (!isDiag) {
#pragma unroll
        for (int off = 4; off <= 16; off <<= 1)
#pragma unroll
            for (int ni = 0; ni < 8; ni++)
#pragma unroll
                for (int h = 0; h < 2; h++)
                    cs[ni][h] += __shfl_xor_sync(0xffffffffu, cs[ni][h], off);
        const int ni = lane >> 2;
        const int c = c0 + warp_n * 64 + ni * 8 + (lane & 3) * 2;
        atomicAdd(&g_rowsum[c],     cs[ni][0]);
        atomicAdd(&g_rowsum[c + 1], cs[ni][1]);
    }
}

// ---------------------------------------------------------------------------
// Kernel 4: nll_i = -pos_i + 10 + log(rowsum_i); out = mean(nll)
// ---------------------------------------------------------------------------
__global__ __launch_bounds__(1024) void final_kernel(float* __restrict__ out) {
    __shared__ float red[1024];
    float s = 0.f;
    for (int i = threadIdx.x; i < NB; i += 1024)
        s += -g_pos[i] + 10.0f + logf(g_rowsum[i]);
    red[threadIdx.x] = s;
    __syncthreads();
    for (int off = 512; off > 0; off >>= 1) {
        if (threadIdx.x < off) red[threadIdx.x] += red[threadIdx.x + off];
        __syncthreads();
    }
    if (threadIdx.x == 0) out[0] = red[0] / (float)NB;
}

// ---------------------------------------------------------------------------
extern "C" void kernel_launch(void* const* d_in, const int* in_sizes, int n_in,
                              void* d_out, int out_size) {
    const float* x = (const float*)d_in[0];
    const float* w = (const float*)d_in[1];
    const float* b = (const float*)d_in[2];
    float* out = (float*)d_out;

    cudaFuncSetAttribute(proj_kernel, cudaFuncAttributeMaxDynamicSharedMemorySize, PROJ_SMEM);
    cudaFuncSetAttribute(sim_kernel,  cudaFuncAttributeMaxDynamicSharedMemorySize, SIM_SMEM);

    convert_kernel<<<XCVT_BLOCKS + WCVT_BLOCKS, 256>>>(x, w);
    dim3 g1(P_DIM / 128, M2 / 128);
    proj_kernel<<<g1, 128, PROJ_SMEM>>>(b);
    norm_kernel<<<NB, 256>>>();
    sim_kernel<<<TRI_BLOCKS, 128, SIM_SMEM>>>();
    final_kernel<<<1, 1024>>>(out);
}